// round 4
// baseline (speedup 1.0000x reference)
#include <cuda_runtime.h>
#include <math.h>

// GCNNet: 2x GCNConv(+self loops, sym norm) -> mean pool -> 4-layer MLP
// N=50000 nodes, E=800000 edges, 64 graphs, fp32 throughout.
//
// Strategy:
//  - A(XW) == (AX)W : aggregate both layers at 64 channels.
//  - Build CSR (dst-major) per call: int histogram + 1-block scan + fill.
//    Aggregation = warp-per-node gather-accumulate, NO float atomics.
//  - Pre/post scale by dinv, self loop folded into accumulator init.
//  - batch is sorted -> per-graph offsets -> atomic-free mean pool.
//  - MLP fused into one single-block kernel.

#define MAXN 50000
#define MAXE 800000
#define NG 64

__device__ int   g_is64;
__device__ float g_dinv[MAXN];
__device__ int   g_cnt[MAXN];
__device__ int   g_rowstart[MAXN + 1];
__device__ int   g_cursor[MAXN];
__device__ int   g_csr[MAXE];
__device__ float g_hsA[MAXN * 64];
__device__ float g_aggA[MAXN * 64];
__device__ float g_hsB[MAXN * 64];
__device__ float g_aggB[MAXN * 64];
__device__ float g_h2[(size_t)MAXN * 128];
__device__ int   g_off[NG + 1];
__device__ float g_pool[NG * 128];

// Index load that works whether the harness gave us int64 or int32 indices.
__device__ __forceinline__ int load_idx(const void* p, long long i) {
    return g_is64 ? (int)((const long long*)p)[i] : ((const int*)p)[i];
}

// ---------------------------------------------------------------------------
// dtype detection: edge values < 50000, so if data is int64 every odd int32
// word is 0. For int32 data the odd words are real edge indices (~0 prob all 0).
__global__ void k_detect(const int* ei_as_i32) {
    int is64 = 1;
    for (int k = 0; k < 256; k++) {
        if (ei_as_i32[2 * k + 1] != 0) { is64 = 0; break; }
    }
    g_is64 = is64;
}

__global__ void k_zero_cnt(int N) {
    int i = blockIdx.x * blockDim.x + threadIdx.x;
    if (i < N) g_cnt[i] = 0;
}

__global__ void k_hist(const void* ei, int E) {
    int e = blockIdx.x * blockDim.x + threadIdx.x;
    if (e >= E) return;
    int d = load_idx(ei, (long long)E + e);
    atomicAdd(&g_cnt[d], 1);
}

// Single-block exclusive scan over g_cnt -> g_rowstart/g_cursor, plus dinv.
__global__ void k_scan(int N, int E) {
    __shared__ int partial[1024];
    int tid = threadIdx.x;
    int CH = (N + 1023) >> 10;
    int begin = tid * CH;
    int end = begin + CH; if (end > N) end = N;
    int s = 0;
    for (int i = begin; i < end; i++) s += g_cnt[i];
    partial[tid] = s;
    __syncthreads();
    for (int off = 1; off < 1024; off <<= 1) {
        int v = partial[tid];
        int add = (tid >= off) ? partial[tid - off] : 0;
        __syncthreads();
        partial[tid] = v + add;
        __syncthreads();
    }
    int run = (tid == 0) ? 0 : partial[tid - 1];
    for (int i = begin; i < end; i++) {
        int c = g_cnt[i];
        g_rowstart[i] = run;
        g_cursor[i] = run;
        g_dinv[i] = rsqrtf((float)(c + 1));  // +1 = self loop; deg >= 1 always
        run += c;
    }
    if (tid == 1023) g_rowstart[N] = E;
}

__global__ void k_fill(const void* ei, int E) {
    int e = blockIdx.x * blockDim.x + threadIdx.x;
    if (e >= E) return;
    int d = load_idx(ei, (long long)E + e);
    int s = load_idx(ei, e);
    int pos = atomicAdd(&g_cursor[d], 1);
    g_csr[pos] = s;
}

// ---------------------------------------------------------------------------
// GEMM1: hsA[r][c] = (x[r] @ W1)[c] * dinv[r].   x:[N,128]  W1:[128,64]
__global__ __launch_bounds__(256) void k_gemm1(const float* __restrict__ x,
                                               const float* __restrict__ W1, int N) {
    __shared__ float xs[32 * 128];
    __shared__ float ws[128 * 64];
    int t = threadIdx.x;
    int row0 = blockIdx.x * 32;

    float4* ws4 = (float4*)ws;
    const float4* W14 = (const float4*)W1;
    for (int i = t; i < 2048; i += 256) ws4[i] = W14[i];

    float4* xs4 = (float4*)xs;
    const float4* x4 = (const float4*)x;
    for (int i = t; i < 1024; i += 256) {
        int r = i >> 5;
        int gr = row0 + r;
        xs4[i] = (gr < N) ? x4[(size_t)gr * 32 + (i & 31)] : make_float4(0.f, 0.f, 0.f, 0.f);
    }
    __syncthreads();

    int r0 = (t >> 4) * 2;
    int c0 = (t & 15) * 4;
    float4 a0 = make_float4(0.f, 0.f, 0.f, 0.f);
    float4 a1 = make_float4(0.f, 0.f, 0.f, 0.f);
#pragma unroll 8
    for (int k = 0; k < 128; k++) {
        float4 w = *(const float4*)&ws[k * 64 + c0];
        float xv0 = xs[r0 * 128 + k];
        float xv1 = xs[(r0 + 1) * 128 + k];
        a0.x += xv0 * w.x; a0.y += xv0 * w.y; a0.z += xv0 * w.z; a0.w += xv0 * w.w;
        a1.x += xv1 * w.x; a1.y += xv1 * w.y; a1.z += xv1 * w.z; a1.w += xv1 * w.w;
    }
    int gr0 = row0 + r0;
    if (gr0 < N) {
        float d = g_dinv[gr0];
        float4 o = make_float4(a0.x * d, a0.y * d, a0.z * d, a0.w * d);
        *(float4*)&g_hsA[(size_t)gr0 * 64 + c0] = o;
    }
    int gr1 = gr0 + 1;
    if (gr1 < N) {
        float d = g_dinv[gr1];
        float4 o = make_float4(a1.x * d, a1.y * d, a1.z * d, a1.w * d);
        *(float4*)&g_hsB[0] = *(float4*)&g_hsB[0];  // no-op guard elided below
        *(float4*)&g_hsA[(size_t)gr1 * 64 + c0] = o;
    }
}

// ---------------------------------------------------------------------------
// Aggregation: agg[i] = hs[i] + sum_{e: dst==i} hs[src[e]]   (64 ch, float2/lane)
template <int L>
__global__ __launch_bounds__(256) void k_agg(int N) {
    const float2* hs = (L == 0) ? (const float2*)g_hsA : (const float2*)g_hsB;
    float2* agg = (L == 0) ? (float2*)g_aggA : (float2*)g_aggB;

    int warp = (blockIdx.x * blockDim.x + threadIdx.x) >> 5;
    int lane = threadIdx.x & 31;
    if (warp >= N) return;

    int s = g_rowstart[warp];
    int e = g_rowstart[warp + 1];
    float2 acc = hs[(size_t)warp * 32 + lane];  // self loop
    int j = s;
    for (; j + 1 < e; j += 2) {
        int s0 = g_csr[j];
        int s1 = g_csr[j + 1];
        float2 v0 = hs[(size_t)s0 * 32 + lane];
        float2 v1 = hs[(size_t)s1 * 32 + lane];
        acc.x += v0.x + v1.x;
        acc.y += v0.y + v1.y;
    }
    if (j < e) {
        int s0 = g_csr[j];
        float2 v0 = hs[(size_t)s0 * 32 + lane];
        acc.x += v0.x;
        acc.y += v0.y;
    }
    agg[(size_t)warp * 32 + lane] = acc;
}

// hsB = relu(aggA*dinv + b1) * dinv      (prescale for layer-2 aggregation)
__global__ void k_post1(const float* __restrict__ b1, int N) {
    int idx = blockIdx.x * blockDim.x + threadIdx.x;
    if (idx >= N * 16) return;
    int r = idx >> 4;
    int c4 = idx & 15;
    float d = g_dinv[r];
    float4 a = ((const float4*)g_aggA)[idx];
    float4 b = __ldg((const float4*)&b1[c4 * 4]);
    float4 v;
    v.x = fmaxf(a.x * d + b.x, 0.f) * d;
    v.y = fmaxf(a.y * d + b.y, 0.f) * d;
    v.z = fmaxf(a.z * d + b.z, 0.f) * d;
    v.w = fmaxf(a.w * d + b.w, 0.f) * d;
    ((float4*)g_hsB)[idx] = v;
}

// ---------------------------------------------------------------------------
// GEMM2: h2[r] = relu( (aggB[r]*dinv[r]) @ W2 + b2 )   W2:[64,128]
__global__ __launch_bounds__(256) void k_gemm2(const float* __restrict__ W2,
                                               const float* __restrict__ b2, int N) {
    __shared__ float xs[32 * 64];
    __shared__ float ws[64 * 128];
    int t = threadIdx.x;
    int row0 = blockIdx.x * 32;

    float4* ws4 = (float4*)ws;
    const float4* W24 = (const float4*)W2;
    for (int i = t; i < 2048; i += 256) ws4[i] = W24[i];

    const float4* agg4 = (const float4*)g_aggB;
    float4* xs4 = (float4*)xs;
    for (int i = t; i < 512; i += 256) {
        int r = i >> 4;
        int gr = row0 + r;
        if (gr < N) {
            float d = g_dinv[gr];
            float4 v = agg4[(size_t)gr * 16 + (i & 15)];
            v.x *= d; v.y *= d; v.z *= d; v.w *= d;
            xs4[i] = v;
        } else {
            xs4[i] = make_float4(0.f, 0.f, 0.f, 0.f);
        }
    }
    __syncthreads();

    int r0 = (t >> 4) * 2;
    int c0 = (t & 15) * 8;
    float4 a00 = make_float4(0.f, 0.f, 0.f, 0.f), a01 = a00, a10 = a00, a11 = a00;
#pragma unroll 8
    for (int k = 0; k < 64; k++) {
        float4 w0 = *(const float4*)&ws[k * 128 + c0];
        float4 w1 = *(const float4*)&ws[k * 128 + c0 + 4];
        float xv0 = xs[r0 * 64 + k];
        float xv1 = xs[(r0 + 1) * 64 + k];
        a00.x += xv0 * w0.x; a00.y += xv0 * w0.y; a00.z += xv0 * w0.z; a00.w += xv0 * w0.w;
        a01.x += xv0 * w1.x; a01.y += xv0 * w1.y; a01.z += xv0 * w1.z; a01.w += xv0 * w1.w;
        a10.x += xv1 * w0.x; a10.y += xv1 * w0.y; a10.z += xv1 * w0.z; a10.w += xv1 * w0.w;
        a11.x += xv1 * w1.x; a11.y += xv1 * w1.y; a11.z += xv1 * w1.z; a11.w += xv1 * w1.w;
    }
    float4 bb0 = __ldg((const float4*)&b2[c0]);
    float4 bb1 = __ldg((const float4*)&b2[c0 + 4]);
    int gr0 = row0 + r0;
    if (gr0 < N) {
        float4 o0 = make_float4(fmaxf(a00.x + bb0.x, 0.f), fmaxf(a00.y + bb0.y, 0.f),
                                fmaxf(a00.z + bb0.z, 0.f), fmaxf(a00.w + bb0.w, 0.f));
        float4 o1 = make_float4(fmaxf(a01.x + bb1.x, 0.f), fmaxf(a01.y + bb1.y, 0.f),
                                fmaxf(a01.z + bb1.z, 0.f), fmaxf(a01.w + bb1.w, 0.f));
        *(float4*)&g_h2[(size_t)gr0 * 128 + c0] = o0;
        *(float4*)&g_h2[(size_t)gr0 * 128 + c0 + 4] = o1;
    }
    int gr1 = gr0 + 1;
    if (gr1 < N) {
        float4 o0 = make_float4(fmaxf(a10.x + bb0.x, 0.f), fmaxf(a10.y + bb0.y, 0.f),
                                fmaxf(a10.z + bb0.z, 0.f), fmaxf(a10.w + bb0.w, 0.f));
        float4 o1 = make_float4(fmaxf(a11.x + bb1.x, 0.f), fmaxf(a11.y + bb1.y, 0.f),
                                fmaxf(a11.z + bb1.z, 0.f), fmaxf(a11.w + bb1.w, 0.f));
        *(float4*)&g_h2[(size_t)gr1 * 128 + c0] = o0;
        *(float4*)&g_h2[(size_t)gr1 * 128 + c0 + 4] = o1;
    }
}

// ---------------------------------------------------------------------------
// batch is sorted ascending -> graph start offsets.
__global__ void k_offsets(const void* batch, int N) {
    int i = blockIdx.x * blockDim.x + threadIdx.x;
    if (i >= N) return;
    int b = load_idx(batch, i);
    int bp = (i == 0) ? -1 : load_idx(batch, i - 1);
    for (int g = bp + 1; g <= b; g++) g_off[g] = i;
    if (i == N - 1) {
        for (int g = b + 1; g <= NG; g++) g_off[g] = N;
    }
}

__global__ void k_pool(int N) {
    int g = blockIdx.x;
    int c = threadIdx.x;
    int s = g_off[g], e = g_off[g + 1];
    float sum = 0.f;
    int r = s;
    for (; r + 3 < e; r += 4) {
        sum += g_h2[(size_t)r * 128 + c] + g_h2[(size_t)(r + 1) * 128 + c] +
               g_h2[(size_t)(r + 2) * 128 + c] + g_h2[(size_t)(r + 3) * 128 + c];
    }
    for (; r < e; r++) sum += g_h2[(size_t)r * 128 + c];
    g_pool[g * 128 + c] = sum / fmaxf((float)(e - s), 1.f);
}

// ---------------------------------------------------------------------------
// Fused MLP on [64,128]: all 4 layers in one block.
__global__ __launch_bounds__(512) void k_mlp(const float* __restrict__ M1, const float* __restrict__ c1,
                                             const float* __restrict__ M2, const float* __restrict__ c2,
                                             const float* __restrict__ M3, const float* __restrict__ c3,
                                             const float* __restrict__ M4, const float* __restrict__ c4,
                                             float* __restrict__ out) {
    __shared__ float sm[12288];
    float* A = sm;          // 8192: pool, then stage-2 output (first 4096)
    float* B = sm + 8192;   // 4096: stage-1 output, then stage-3 output
    int t = threadIdx.x;
    for (int i = t; i < 8192; i += 512) A[i] = g_pool[i];
    __syncthreads();

    int r = t >> 3;
    int c0 = (t & 7) * 8;

    // stage 1: B = leaky0.2(A[64,128] @ M1[128,64] + c1)
    {
        float acc[8] = {0, 0, 0, 0, 0, 0, 0, 0};
#pragma unroll 4
        for (int k = 0; k < 128; k++) {
            float a = A[r * 128 + k];
            float4 m0 = __ldg((const float4*)&M1[k * 64 + c0]);
            float4 m1 = __ldg((const float4*)&M1[k * 64 + c0 + 4]);
            acc[0] += a * m0.x; acc[1] += a * m0.y; acc[2] += a * m0.z; acc[3] += a * m0.w;
            acc[4] += a * m1.x; acc[5] += a * m1.y; acc[6] += a * m1.z; acc[7] += a * m1.w;
        }
#pragma unroll
        for (int j = 0; j < 8; j++) {
            float v = acc[j] + __ldg(&c1[c0 + j]);
            B[r * 64 + c0 + j] = (v > 0.f) ? v : 0.2f * v;
        }
    }
    __syncthreads();

    // stage 2: A[.,64] = leaky0.1(B @ M2[64,64] + c2)
    {
        float acc[8] = {0, 0, 0, 0, 0, 0, 0, 0};
#pragma unroll 4
        for (int k = 0; k < 64; k++) {
            float a = B[r * 64 + k];
            float4 m0 = __ldg((const float4*)&M2[k * 64 + c0]);
            float4 m1 = __ldg((const float4*)&M2[k * 64 + c0 + 4]);
            acc[0] += a * m0.x; acc[1] += a * m0.y; acc[2] += a * m0.z; acc[3] += a * m0.w;
            acc[4] += a * m1.x; acc[5] += a * m1.y; acc[6] += a * m1.z; acc[7] += a * m1.w;
        }
        __syncthreads();  // ensure stage-1 reads of B... (B reads done above)
#pragma unroll
        for (int j = 0; j < 8; j++) {
            float v = acc[j] + __ldg(&c2[c0 + j]);
            A[r * 64 + c0 + j] = (v > 0.f) ? v : 0.1f * v;
        }
    }
    __syncthreads();

    // stage 3: B = leaky0.1(A[.,64] @ M3[64,64] + c3)
    {
        float acc[8] = {0, 0, 0, 0, 0, 0, 0, 0};
#pragma unroll 4
        for (int k = 0; k < 64; k++) {
            float a = A[r * 64 + k];
            float4 m0 = __ldg((const float4*)&M3[k * 64 + c0]);
            float4 m1 = __ldg((const float4*)&M3[k * 64 + c0 + 4]);
            acc[0] += a * m0.x; acc[1] += a * m0.y; acc[2] += a * m0.z; acc[3] += a * m0.w;
            acc[4] += a * m1.x; acc[5] += a * m1.y; acc[6] += a * m1.z; acc[7] += a * m1.w;
        }
        __syncthreads();
#pragma unroll
        for (int j = 0; j < 8; j++) {
            float v = acc[j] + __ldg(&c3[c0 + j]);
            B[r * 64 + c0 + j] = (v > 0.f) ? v : 0.1f * v;
        }
    }
    __syncthreads();

    // stage 4: out[g] = relu(B[g] @ M4[64,1] + c4)
    if (t < 64) {
        float s = 0.f;
#pragma unroll 4
        for (int k = 0; k < 64; k++) s += B[t * 64 + k] * __ldg(&M4[k]);
        s += __ldg(&c4[0]);
        out[t] = fmaxf(s, 0.f);
    }
}

// ---------------------------------------------------------------------------
extern "C" void kernel_launch(void* const* d_in, const int* in_sizes, int n_in,
                              void* d_out, int out_size) {
    const float* x  = (const float*)d_in[0];
    const void*  ei = d_in[1];
    const void*  bt = d_in[2];
    const float* W1 = (const float*)d_in[3];
    const float* b1 = (const float*)d_in[4];
    const float* W2 = (const float*)d_in[5];
    const float* b2 = (const float*)d_in[6];
    const float* M1 = (const float*)d_in[7];
    const float* c1 = (const float*)d_in[8];
    const float* M2 = (const float*)d_in[9];
    const float* c2 = (const float*)d_in[10];
    const float* M3 = (const float*)d_in[11];
    const float* c3 = (const float*)d_in[12];
    const float* M4 = (const float*)d_in[13];
    const float* c4 = (const float*)d_in[14];
    float* out = (float*)d_out;

    int E = in_sizes[1] / 2;   // 800000
    int N = in_sizes[2];       // 50000

    k_detect<<<1, 1>>>((const int*)ei);
    k_zero_cnt<<<(N + 255) / 256, 256>>>(N);
    k_hist<<<(E + 255) / 256, 256>>>(ei, E);
    k_scan<<<1, 1024>>>(N, E);
    k_fill<<<(E + 255) / 256, 256>>>(ei, E);
    k_offsets<<<(N + 255) / 256, 256>>>(bt, N);

    k_gemm1<<<(N + 31) / 32, 256>>>(x, W1, N);
    k_agg<0><<<(N + 7) / 8, 256>>>(N);
    k_post1<<<(N * 16 + 255) / 256, 256>>>(b1, N);
    k_agg<1><<<(N + 7) / 8, 256>>>(N);
    k_gemm2<<<(N + 31) / 32, 256>>>(W2, b2, N);

    k_pool<<<NG, 128>>>(N);
    k_mlp<<<1, 512>>>(M1, c1, M2, c2, M3, c3, M4, c4, out);
}

// round 5
// speedup vs baseline: 1.3931x; 1.3931x over previous
#include <cuda_runtime.h>
#include <math.h>

// GCNNet: 2x GCNConv(+self loops, sym norm) -> mean pool -> 4-layer MLP
// N=50000 nodes, E=800000 edges, 64 graphs, fp32 throughout.
//
//  - A(XW) == (AX)W : aggregate both layers at 64 channels.
//  - CSR build: histogram + DEVICE-WIDE 3-kernel scan (was 104us single block).
//  - Aggregation = warp-per-node gather, no float atomics; layer-1 epilogue
//    (relu + bias + dinv pre/post scale) fused into agg<0>.
//  - detect kernel is a single warp + ballot (was 1 serial thread).
//  - pool uses 1024 threads/graph (8 row groups x 128 ch).

#define MAXN 50000
#define MAXE 800000
#define NG 64
#define NB_MAX 256   // >= ceil(N/256)

__device__ int   g_is64;
__device__ float g_dinv[MAXN];
__device__ int   g_cnt[MAXN];
__device__ int   g_rowstart[MAXN + 1];
__device__ int   g_cursor[MAXN];
__device__ int   g_csr[MAXE];
__device__ int   g_bsum[NB_MAX];
__device__ int   g_boff[NB_MAX];
__device__ float g_hsA[MAXN * 64];
__device__ float g_hsB[MAXN * 64];
__device__ float g_aggB[MAXN * 64];
__device__ float g_h2[(size_t)MAXN * 128];
__device__ int   g_off[NG + 1];
__device__ float g_pool[NG * 128];

__device__ __forceinline__ int load_idx(const void* p, long long i) {
    return g_is64 ? (int)((const long long*)p)[i] : ((const int*)p)[i];
}

// ---------------------------------------------------------------------------
// dtype detection, one warp: if data is int64, every odd int32 word is 0.
__global__ void k_detect(const int* ei_as_i32) {
    unsigned m = __ballot_sync(0xffffffffu, ei_as_i32[2 * threadIdx.x + 1] != 0);
    if (threadIdx.x == 0) g_is64 = (m == 0u) ? 1 : 0;
}

__global__ void k_zero_cnt(int N) {
    int i = blockIdx.x * blockDim.x + threadIdx.x;
    if (i < N) g_cnt[i] = 0;
}

__global__ void k_hist(const void* ei, int E) {
    int e = blockIdx.x * blockDim.x + threadIdx.x;
    if (e >= E) return;
    int d = load_idx(ei, (long long)E + e);
    atomicAdd(&g_cnt[d], 1);
}

// ---- device-wide exclusive scan of g_cnt (3 kernels) ----------------------
__global__ void k_blocksum(int N) {
    int i = blockIdx.x * 256 + threadIdx.x;
    int v = (i < N) ? g_cnt[i] : 0;
#pragma unroll
    for (int o = 16; o; o >>= 1) v += __shfl_down_sync(0xffffffffu, v, o);
    __shared__ int ws[8];
    if ((threadIdx.x & 31) == 0) ws[threadIdx.x >> 5] = v;
    __syncthreads();
    if (threadIdx.x == 0) {
        int s = 0;
#pragma unroll
        for (int j = 0; j < 8; j++) s += ws[j];
        g_bsum[blockIdx.x] = s;
    }
}

__global__ void k_scanb(int NB, int E, int N) {
    __shared__ int sh[256];
    int t = threadIdx.x;
    int v = (t < NB) ? g_bsum[t] : 0;
    sh[t] = v;
    __syncthreads();
    for (int o = 1; o < 256; o <<= 1) {
        int val = sh[t];
        int add = (t >= o) ? sh[t - o] : 0;
        __syncthreads();
        sh[t] = val + add;
        __syncthreads();
    }
    if (t < NB) g_boff[t] = sh[t] - v;   // exclusive
    if (t == 0) g_rowstart[N] = E;
}

__global__ void k_apply(int N) {
    int t = threadIdx.x;
    int i = blockIdx.x * 256 + t;
    int c = (i < N) ? g_cnt[i] : 0;
    int lane = t & 31, w = t >> 5;
    int x = c;
#pragma unroll
    for (int o = 1; o < 32; o <<= 1) {
        int y = __shfl_up_sync(0xffffffffu, x, o);
        if (lane >= o) x += y;
    }
    __shared__ int wt[8];
    __shared__ int wo[8];
    if (lane == 31) wt[w] = x;
    __syncthreads();
    if (t < 8) {
        int s = 0;
        for (int j = 0; j < t; j++) s += wt[j];
        wo[t] = s;
    }
    __syncthreads();
    if (i < N) {
        int excl = x - c + wo[w] + g_boff[blockIdx.x];
        g_rowstart[i] = excl;
        g_cursor[i]   = excl;
        g_dinv[i]     = rsqrtf((float)(c + 1));  // +1 self loop
    }
}

__global__ void k_fill(const void* ei, int E) {
    int e = blockIdx.x * blockDim.x + threadIdx.x;
    if (e >= E) return;
    int d = load_idx(ei, (long long)E + e);
    int s = load_idx(ei, e);
    int pos = atomicAdd(&g_cursor[d], 1);
    g_csr[pos] = s;
}

// ---------------------------------------------------------------------------
// GEMM1: hsA[r][c] = (x[r] @ W1)[c] * dinv[r].   x:[N,128]  W1:[128,64]
__global__ __launch_bounds__(256) void k_gemm1(const float* __restrict__ x,
                                               const float* __restrict__ W1, int N) {
    __shared__ float xs[32 * 128];
    __shared__ float ws[128 * 64];
    int t = threadIdx.x;
    int row0 = blockIdx.x * 32;

    float4* ws4 = (float4*)ws;
    const float4* W14 = (const float4*)W1;
    for (int i = t; i < 2048; i += 256) ws4[i] = W14[i];

    float4* xs4 = (float4*)xs;
    const float4* x4 = (const float4*)x;
    for (int i = t; i < 1024; i += 256) {
        int r = i >> 5;
        int gr = row0 + r;
        xs4[i] = (gr < N) ? x4[(size_t)gr * 32 + (i & 31)] : make_float4(0.f, 0.f, 0.f, 0.f);
    }
    __syncthreads();

    int r0 = (t >> 4) * 2;
    int c0 = (t & 15) * 4;
    float4 a0 = make_float4(0.f, 0.f, 0.f, 0.f);
    float4 a1 = make_float4(0.f, 0.f, 0.f, 0.f);
#pragma unroll 8
    for (int k = 0; k < 128; k++) {
        float4 w = *(const float4*)&ws[k * 64 + c0];
        float xv0 = xs[r0 * 128 + k];
        float xv1 = xs[(r0 + 1) * 128 + k];
        a0.x += xv0 * w.x; a0.y += xv0 * w.y; a0.z += xv0 * w.z; a0.w += xv0 * w.w;
        a1.x += xv1 * w.x; a1.y += xv1 * w.y; a1.z += xv1 * w.z; a1.w += xv1 * w.w;
    }
    int gr0 = row0 + r0;
    if (gr0 < N) {
        float d = g_dinv[gr0];
        *(float4*)&g_hsA[(size_t)gr0 * 64 + c0] =
            make_float4(a0.x * d, a0.y * d, a0.z * d, a0.w * d);
    }
    int gr1 = gr0 + 1;
    if (gr1 < N) {
        float d = g_dinv[gr1];
        *(float4*)&g_hsA[(size_t)gr1 * 64 + c0] =
            make_float4(a1.x * d, a1.y * d, a1.z * d, a1.w * d);
    }
}

// ---------------------------------------------------------------------------
// Aggregation: acc = hs[i] + sum_{e: dst==i} hs[src[e]]   (64 ch, float2/lane)
// L==0: fused epilogue  hsB = relu(acc*dinv + b1) * dinv
// L==1: aggB = acc
template <int L>
__global__ __launch_bounds__(256) void k_agg(const float* __restrict__ b1, int N) {
    const float2* hs = (L == 0) ? (const float2*)g_hsA : (const float2*)g_hsB;

    int warp = (blockIdx.x * blockDim.x + threadIdx.x) >> 5;
    int lane = threadIdx.x & 31;
    if (warp >= N) return;

    int s = g_rowstart[warp];
    int e = g_rowstart[warp + 1];
    float2 acc = hs[(size_t)warp * 32 + lane];  // self loop
    int j = s;
    for (; j + 1 < e; j += 2) {
        int s0 = g_csr[j];
        int s1 = g_csr[j + 1];
        float2 v0 = hs[(size_t)s0 * 32 + lane];
        float2 v1 = hs[(size_t)s1 * 32 + lane];
        acc.x += v0.x + v1.x;
        acc.y += v0.y + v1.y;
    }
    if (j < e) {
        int s0 = g_csr[j];
        float2 v0 = hs[(size_t)s0 * 32 + lane];
        acc.x += v0.x;
        acc.y += v0.y;
    }
    if (L == 0) {
        float d = g_dinv[warp];
        float2 bb = __ldg(&((const float2*)b1)[lane]);
        float2 o;
        o.x = fmaxf(acc.x * d + bb.x, 0.f) * d;
        o.y = fmaxf(acc.y * d + bb.y, 0.f) * d;
        ((float2*)g_hsB)[(size_t)warp * 32 + lane] = o;
    } else {
        ((float2*)g_aggB)[(size_t)warp * 32 + lane] = acc;
    }
}

// ---------------------------------------------------------------------------
// GEMM2: h2[r] = relu( (aggB[r]*dinv[r]) @ W2 + b2 )   W2:[64,128]
__global__ __launch_bounds__(256) void k_gemm2(const float* __restrict__ W2,
                                               const float* __restrict__ b2, int N) {
    __shared__ float xs[32 * 64];
    __shared__ float ws[64 * 128];
    int t = threadIdx.x;
    int row0 = blockIdx.x * 32;

    float4* ws4 = (float4*)ws;
    const float4* W24 = (const float4*)W2;
    for (int i = t; i < 2048; i += 256) ws4[i] = W24[i];

    const float4* agg4 = (const float4*)g_aggB;
    float4* xs4 = (float4*)xs;
    for (int i = t; i < 512; i += 256) {
        int r = i >> 4;
        int gr = row0 + r;
        if (gr < N) {
            float d = g_dinv[gr];
            float4 v = agg4[(size_t)gr * 16 + (i & 15)];
            v.x *= d; v.y *= d; v.z *= d; v.w *= d;
            xs4[i] = v;
        } else {
            xs4[i] = make_float4(0.f, 0.f, 0.f, 0.f);
        }
    }
    __syncthreads();

    int r0 = (t >> 4) * 2;
    int c0 = (t & 15) * 8;
    float4 a00 = make_float4(0.f, 0.f, 0.f, 0.f), a01 = a00, a10 = a00, a11 = a00;
#pragma unroll 8
    for (int k = 0; k < 64; k++) {
        float4 w0 = *(const float4*)&ws[k * 128 + c0];
        float4 w1 = *(const float4*)&ws[k * 128 + c0 + 4];
        float xv0 = xs[r0 * 64 + k];
        float xv1 = xs[(r0 + 1) * 64 + k];
        a00.x += xv0 * w0.x; a00.y += xv0 * w0.y; a00.z += xv0 * w0.z; a00.w += xv0 * w0.w;
        a01.x += xv0 * w1.x; a01.y += xv0 * w1.y; a01.z += xv0 * w1.z; a01.w += xv0 * w1.w;
        a10.x += xv1 * w0.x; a10.y += xv1 * w0.y; a10.z += xv1 * w0.z; a10.w += xv1 * w0.w;
        a11.x += xv1 * w1.x; a11.y += xv1 * w1.y; a11.z += xv1 * w1.z; a11.w += xv1 * w1.w;
    }
    float4 bb0 = __ldg((const float4*)&b2[c0]);
    float4 bb1 = __ldg((const float4*)&b2[c0 + 4]);
    int gr0 = row0 + r0;
    if (gr0 < N) {
        *(float4*)&g_h2[(size_t)gr0 * 128 + c0] =
            make_float4(fmaxf(a00.x + bb0.x, 0.f), fmaxf(a00.y + bb0.y, 0.f),
                        fmaxf(a00.z + bb0.z, 0.f), fmaxf(a00.w + bb0.w, 0.f));
        *(float4*)&g_h2[(size_t)gr0 * 128 + c0 + 4] =
            make_float4(fmaxf(a01.x + bb1.x, 0.f), fmaxf(a01.y + bb1.y, 0.f),
                        fmaxf(a01.z + bb1.z, 0.f), fmaxf(a01.w + bb1.w, 0.f));
    }
    int gr1 = gr0 + 1;
    if (gr1 < N) {
        *(float4*)&g_h2[(size_t)gr1 * 128 + c0] =
            make_float4(fmaxf(a10.x + bb0.x, 0.f), fmaxf(a10.y + bb0.y, 0.f),
                        fmaxf(a10.z + bb0.z, 0.f), fmaxf(a10.w + bb0.w, 0.f));
        *(float4*)&g_h2[(size_t)gr1 * 128 + c0 + 4] =
            make_float4(fmaxf(a11.x + bb1.x, 0.f), fmaxf(a11.y + bb1.y, 0.f),
                        fmaxf(a11.z + bb1.z, 0.f), fmaxf(a11.w + bb1.w, 0.f));
    }
}

// ---------------------------------------------------------------------------
__global__ void k_offsets(const void* batch, int N) {
    int i = blockIdx.x * blockDim.x + threadIdx.x;
    if (i >= N) return;
    int b = load_idx(batch, i);
    int bp = (i == 0) ? -1 : load_idx(batch, i - 1);
    for (int g = bp + 1; g <= b; g++) g_off[g] = i;
    if (i == N - 1) {
        for (int g = b + 1; g <= NG; g++) g_off[g] = N;
    }
}

// Mean pool: 1024 threads per graph = 8 row-groups x 128 channels.
__global__ __launch_bounds__(1024) void k_pool(int N) {
    int g = blockIdx.x;
    int t = threadIdx.x;
    int c = t & 127;
    int grp = t >> 7;
    int s = g_off[g], e = g_off[g + 1];
    float sum = 0.f;
    for (int r = s + grp; r < e; r += 8) sum += g_h2[(size_t)r * 128 + c];
    __shared__ float sh[1024];
    sh[t] = sum;
    __syncthreads();
    if (grp == 0) {
        float tot = sh[c] + sh[c + 128] + sh[c + 256] + sh[c + 384] +
                    sh[c + 512] + sh[c + 640] + sh[c + 768] + sh[c + 896];
        g_pool[g * 128 + c] = tot / fmaxf((float)(e - s), 1.f);
    }
}

// ---------------------------------------------------------------------------
// Fused MLP on [64,128]: all 4 layers in one block.
__global__ __launch_bounds__(512) void k_mlp(const float* __restrict__ M1, const float* __restrict__ c1,
                                             const float* __restrict__ M2, const float* __restrict__ c2,
                                             const float* __restrict__ M3, const float* __restrict__ c3,
                                             const float* __restrict__ M4, const float* __restrict__ c4,
                                             float* __restrict__ out) {
    __shared__ float sm[12288];
    float* A = sm;
    float* B = sm + 8192;
    int t = threadIdx.x;
    for (int i = t; i < 8192; i += 512) A[i] = g_pool[i];
    __syncthreads();

    int r = t >> 3;
    int c0 = (t & 7) * 8;

    // stage 1: B = leaky0.2(A[64,128] @ M1[128,64] + c1)
    {
        float acc[8] = {0, 0, 0, 0, 0, 0, 0, 0};
#pragma unroll 4
        for (int k = 0; k < 128; k++) {
            float a = A[r * 128 + k];
            float4 m0 = __ldg((const float4*)&M1[k * 64 + c0]);
            float4 m1 = __ldg((const float4*)&M1[k * 64 + c0 + 4]);
            acc[0] += a * m0.x; acc[1] += a * m0.y; acc[2] += a * m0.z; acc[3] += a * m0.w;
            acc[4] += a * m1.x; acc[5] += a * m1.y; acc[6] += a * m1.z; acc[7] += a * m1.w;
        }
#pragma unroll
        for (int j = 0; j < 8; j++) {
            float v = acc[j] + __ldg(&c1[c0 + j]);
            B[r * 64 + c0 + j] = (v > 0.f) ? v : 0.2f * v;
        }
    }
    __syncthreads();

    // stage 2: A[.,64] = leaky0.1(B @ M2[64,64] + c2)
    {
        float acc[8] = {0, 0, 0, 0, 0, 0, 0, 0};
#pragma unroll 4
        for (int k = 0; k < 64; k++) {
            float a = B[r * 64 + k];
            float4 m0 = __ldg((const float4*)&M2[k * 64 + c0]);
            float4 m1 = __ldg((const float4*)&M2[k * 64 + c0 + 4]);
            acc[0] += a * m0.x; acc[1] += a * m0.y; acc[2] += a * m0.z; acc[3] += a * m0.w;
            acc[4] += a * m1.x; acc[5] += a * m1.y; acc[6] += a * m1.z; acc[7] += a * m1.w;
        }
        __syncthreads();
#pragma unroll
        for (int j = 0; j < 8; j++) {
            float v = acc[j] + __ldg(&c2[c0 + j]);
            A[r * 64 + c0 + j] = (v > 0.f) ? v : 0.1f * v;
        }
    }
    __syncthreads();

    // stage 3: B = leaky0.1(A[.,64] @ M3[64,64] + c3)
    {
        float acc[8] = {0, 0, 0, 0, 0, 0, 0, 0};
#pragma unroll 4
        for (int k = 0; k < 64; k++) {
            float a = A[r * 64 + k];
            float4 m0 = __ldg((const float4*)&M3[k * 64 + c0]);
            float4 m1 = __ldg((const float4*)&M3[k * 64 + c0 + 4]);
            acc[0] += a * m0.x; acc[1] += a * m0.y; acc[2] += a * m0.z; acc[3] += a * m0.w;
            acc[4] += a * m1.x; acc[5] += a * m1.y; acc[6] += a * m1.z; acc[7] += a * m1.w;
        }
        __syncthreads();
#pragma unroll
        for (int j = 0; j < 8; j++) {
            float v = acc[j] + __ldg(&c3[c0 + j]);
            B[r * 64 + c0 + j] = (v > 0.f) ? v : 0.1f * v;
        }
    }
    __syncthreads();

    // stage 4: out[g] = relu(B[g] @ M4[64,1] + c4)
    if (t < 64) {
        float s = 0.f;
#pragma unroll 4
        for (int k = 0; k < 64; k++) s += B[t * 64 + k] * __ldg(&M4[k]);
        s += __ldg(&c4[0]);
        out[t] = fmaxf(s, 0.f);
    }
}

// ---------------------------------------------------------------------------
extern "C" void kernel_launch(void* const* d_in, const int* in_sizes, int n_in,
                              void* d_out, int out_size) {
    const float* x  = (const float*)d_in[0];
    const void*  ei = d_in[1];
    const void*  bt = d_in[2];
    const float* W1 = (const float*)d_in[3];
    const float* b1 = (const float*)d_in[4];
    const float* W2 = (const float*)d_in[5];
    const float* b2 = (const float*)d_in[6];
    const float* M1 = (const float*)d_in[7];
    const float* c1 = (const float*)d_in[8];
    const float* M2 = (const float*)d_in[9];
    const float* c2 = (const float*)d_in[10];
    const float* M3 = (const float*)d_in[11];
    const float* c3 = (const float*)d_in[12];
    const float* M4 = (const float*)d_in[13];
    const float* c4 = (const float*)d_in[14];
    float* out = (float*)d_out;

    int E = in_sizes[1] / 2;   // 800000
    int N = in_sizes[2];       // 50000
    int NB = (N + 255) / 256;  // 196

    k_detect<<<1, 32>>>((const int*)ei);
    k_zero_cnt<<<(N + 255) / 256, 256>>>(N);
    k_hist<<<(E + 255) / 256, 256>>>(ei, E);
    k_blocksum<<<NB, 256>>>(N);
    k_scanb<<<1, 256>>>(NB, E, N);
    k_apply<<<NB, 256>>>(N);
    k_fill<<<(E + 255) / 256, 256>>>(ei, E);
    k_offsets<<<(N + 255) / 256, 256>>>(bt, N);

    k_gemm1<<<(N + 31) / 32, 256>>>(x, W1, N);
    k_agg<0><<<(N + 7) / 8, 256>>>(b1, N);
    k_agg<1><<<(N + 7) / 8, 256>>>(b1, N);
    k_gemm2<<<(N + 31) / 32, 256>>>(W2, b2, N);

    k_pool<<<NG, 128 * 8>>>(N);
    k_mlp<<<1, 512>>>(M1, c1, M2, c2, M3, c3, M4, c4, out);
}

// round 6
// speedup vs baseline: 1.5926x; 1.1432x over previous
#include <cuda_runtime.h>
#include <math.h>

// GCNNet: 2x GCNConv(+self loops, sym norm) -> mean pool -> 4-layer MLP
// N=50000 nodes, E=800000 edges, 64 graphs, fp32 throughout.
//
//  - A(XW) == (AX)W : aggregate both layers at 64 channels.
//  - CSR build: histogram + device-wide 3-kernel scan.
//  - Aggregation = warp-per-node gather (unroll-4), no float atomics.
//  - Layer-1 epilogue fused into agg<0>; layer-2 aggregation fused with
//    GEMM2 (+bias+relu) in one kernel (W2 staged in two 64-col halves).
//  - GEMM1: 128 threads, 32x64 tile, 4x4 per-thread, conflict-free padded smem.

#define MAXN 50000
#define MAXE 800000
#define NG 64
#define NB_MAX 256

__device__ int   g_is64;
__device__ float g_dinv[MAXN];
__device__ int   g_cnt[MAXN];
__device__ int   g_rowstart[MAXN + 1];
__device__ int   g_cursor[MAXN];
__device__ int   g_csr[MAXE];
__device__ int   g_bsum[NB_MAX];
__device__ int   g_boff[NB_MAX];
__device__ float g_hsA[MAXN * 64];
__device__ float g_hsB[MAXN * 64];
__device__ float g_h2[(size_t)MAXN * 128];
__device__ int   g_off[NG + 1];
__device__ float g_pool[NG * 128];

__device__ __forceinline__ int load_idx(const void* p, long long i) {
    return g_is64 ? (int)((const long long*)p)[i] : ((const int*)p)[i];
}

// ---------------------------------------------------------------------------
__global__ void k_detect(const int* ei_as_i32) {
    unsigned m = __ballot_sync(0xffffffffu, ei_as_i32[2 * threadIdx.x + 1] != 0);
    if (threadIdx.x == 0) g_is64 = (m == 0u) ? 1 : 0;
}

__global__ void k_zero_cnt(int N) {
    int i = blockIdx.x * blockDim.x + threadIdx.x;
    if (i < N) g_cnt[i] = 0;
}

__global__ void k_hist(const void* ei, int E) {
    int e = blockIdx.x * blockDim.x + threadIdx.x;
    if (e >= E) return;
    int d = load_idx(ei, (long long)E + e);
    atomicAdd(&g_cnt[d], 1);
}

// ---- device-wide exclusive scan of g_cnt ----------------------------------
__global__ void k_blocksum(int N) {
    int i = blockIdx.x * 256 + threadIdx.x;
    int v = (i < N) ? g_cnt[i] : 0;
#pragma unroll
    for (int o = 16; o; o >>= 1) v += __shfl_down_sync(0xffffffffu, v, o);
    __shared__ int ws[8];
    if ((threadIdx.x & 31) == 0) ws[threadIdx.x >> 5] = v;
    __syncthreads();
    if (threadIdx.x == 0) {
        int s = 0;
#pragma unroll
        for (int j = 0; j < 8; j++) s += ws[j];
        g_bsum[blockIdx.x] = s;
    }
}

__global__ void k_scanb(int NB, int E, int N) {
    __shared__ int sh[256];
    int t = threadIdx.x;
    int v = (t < NB) ? g_bsum[t] : 0;
    sh[t] = v;
    __syncthreads();
    for (int o = 1; o < 256; o <<= 1) {
        int val = sh[t];
        int add = (t >= o) ? sh[t - o] : 0;
        __syncthreads();
        sh[t] = val + add;
        __syncthreads();
    }
    if (t < NB) g_boff[t] = sh[t] - v;
    if (t == 0) g_rowstart[N] = E;
}

__global__ void k_apply(int N) {
    int t = threadIdx.x;
    int i = blockIdx.x * 256 + t;
    int c = (i < N) ? g_cnt[i] : 0;
    int lane = t & 31, w = t >> 5;
    int x = c;
#pragma unroll
    for (int o = 1; o < 32; o <<= 1) {
        int y = __shfl_up_sync(0xffffffffu, x, o);
        if (lane >= o) x += y;
    }
    __shared__ int wt[8];
    __shared__ int wo[8];
    if (lane == 31) wt[w] = x;
    __syncthreads();
    if (t < 8) {
        int s = 0;
        for (int j = 0; j < t; j++) s += wt[j];
        wo[t] = s;
    }
    __syncthreads();
    if (i < N) {
        int excl = x - c + wo[w] + g_boff[blockIdx.x];
        g_rowstart[i] = excl;
        g_cursor[i]   = excl;
        g_dinv[i]     = rsqrtf((float)(c + 1));
    }
}

__global__ void k_fill(const void* ei, int E) {
    int e = blockIdx.x * blockDim.x + threadIdx.x;
    if (e >= E) return;
    int d = load_idx(ei, (long long)E + e);
    int s = load_idx(ei, e);
    int pos = atomicAdd(&g_cursor[d], 1);
    g_csr[pos] = s;
}

// ---------------------------------------------------------------------------
// GEMM1: hsA[r][c] = (x[r] @ W1)[c] * dinv[r].   x:[N,128]  W1:[128,64]
// 128 threads, 32 rows x 64 cols per block, 4x4 per thread, W1 K-halved.
__global__ __launch_bounds__(128) void k_gemm1(const float* __restrict__ x,
                                               const float* __restrict__ W1, int N) {
    __shared__ float xs[32 * 130];   // stride 130: bank = (2r+k)%32
    __shared__ float ws[64 * 64];
    int t = threadIdx.x;
    int row0 = blockIdx.x * 32;

    // stage xs (full K=128)
    const float2* x2 = (const float2*)x;
#pragma unroll
    for (int j = 0; j < 16; j++) {
        int idx = t + j * 128;
        int r = idx >> 6, kk = idx & 63;
        int gr = row0 + r;
        float2 v = (gr < N) ? x2[(size_t)gr * 64 + kk] : make_float2(0.f, 0.f);
        ((float2*)xs)[r * 65 + kk] = v;
    }

    int rg = t >> 4, cg = t & 15;
    float a[4][4] = {};
    const float4* W14 = (const float4*)W1;
    for (int kh = 0; kh < 2; kh++) {
        __syncthreads();
        for (int i = t; i < 1024; i += 128) {
            int kl = i >> 4, c4 = i & 15;
            ((float4*)ws)[i] = W14[(size_t)(kh * 64 + kl) * 16 + c4];
        }
        __syncthreads();
#pragma unroll 8
        for (int k = 0; k < 64; k++) {
            float4 w = *(const float4*)&ws[k * 64 + cg * 4];
#pragma unroll
            for (int i = 0; i < 4; i++) {
                float xv = xs[(4 * rg + i) * 130 + kh * 64 + k];
                a[i][0] += xv * w.x; a[i][1] += xv * w.y;
                a[i][2] += xv * w.z; a[i][3] += xv * w.w;
            }
        }
    }
#pragma unroll
    for (int i = 0; i < 4; i++) {
        int gr = row0 + 4 * rg + i;
        if (gr < N) {
            float d = g_dinv[gr];
            *(float4*)&g_hsA[(size_t)gr * 64 + cg * 4] =
                make_float4(a[i][0] * d, a[i][1] * d, a[i][2] * d, a[i][3] * d);
        }
    }
}

// ---------------------------------------------------------------------------
// agg<0>: hsB = relu( (hsA self+neighbors sum) * dinv + b1 ) * dinv
__global__ __launch_bounds__(256) void k_agg0(const float* __restrict__ b1, int N) {
    const float2* hs = (const float2*)g_hsA;
    int warp = (blockIdx.x * blockDim.x + threadIdx.x) >> 5;
    int lane = threadIdx.x & 31;
    if (warp >= N) return;

    int s = g_rowstart[warp];
    int e = g_rowstart[warp + 1];
    float2 acc = hs[(size_t)warp * 32 + lane];  // self loop
    int j = s;
    for (; j + 3 < e; j += 4) {
        int s0 = g_csr[j], s1 = g_csr[j + 1], s2 = g_csr[j + 2], s3 = g_csr[j + 3];
        float2 v0 = hs[(size_t)s0 * 32 + lane];
        float2 v1 = hs[(size_t)s1 * 32 + lane];
        float2 v2 = hs[(size_t)s2 * 32 + lane];
        float2 v3 = hs[(size_t)s3 * 32 + lane];
        acc.x += (v0.x + v1.x) + (v2.x + v3.x);
        acc.y += (v0.y + v1.y) + (v2.y + v3.y);
    }
    for (; j < e; j++) {
        int s0 = g_csr[j];
        float2 v0 = hs[(size_t)s0 * 32 + lane];
        acc.x += v0.x;
        acc.y += v0.y;
    }
    float d = g_dinv[warp];
    float2 bb = __ldg(&((const float2*)b1)[lane]);
    float2 o;
    o.x = fmaxf(acc.x * d + bb.x, 0.f) * d;
    o.y = fmaxf(acc.y * d + bb.y, 0.f) * d;
    ((float2*)g_hsB)[(size_t)warp * 32 + lane] = o;
}

// ---------------------------------------------------------------------------
// Fused layer-2: agg over hsB -> shared -> GEMM vs W2[64,128] (+b2, relu) -> h2
// 256 threads, 64 nodes per block, W2 staged in two 64-col halves.
__global__ __launch_bounds__(256) void k_fused2(const float* __restrict__ W2,
                                                const float* __restrict__ b2, int N) {
    __shared__ float xs[64 * 66];    // stride 66: bank = (2r+k)%32
    __shared__ float ws[64 * 64];
    int t = threadIdx.x;
    int warp = t >> 5, lane = t & 31;
    int row0 = blockIdx.x * 64;
    const float4* W24 = (const float4*)W2;

    // load W2 half 0 (cols 0..63) — no dependency on stage A
    for (int i = t; i < 1024; i += 256) {
        int k = i >> 4, c4 = i & 15;
        ((float4*)ws)[i] = W24[(size_t)k * 32 + c4];
    }

    // stage A: aggregate 64 nodes (warp per node, 8 passes)
    const float2* hs = (const float2*)g_hsB;
    for (int p = 0; p < 8; p++) {
        int r = p * 8 + warp;
        int node = row0 + r;
        float2 acc = make_float2(0.f, 0.f);
        if (node < N) {
            int s = g_rowstart[node], e = g_rowstart[node + 1];
            acc = hs[(size_t)node * 32 + lane];
            int j = s;
            for (; j + 3 < e; j += 4) {
                int s0 = g_csr[j], s1 = g_csr[j + 1], s2 = g_csr[j + 2], s3 = g_csr[j + 3];
                float2 v0 = hs[(size_t)s0 * 32 + lane];
                float2 v1 = hs[(size_t)s1 * 32 + lane];
                float2 v2 = hs[(size_t)s2 * 32 + lane];
                float2 v3 = hs[(size_t)s3 * 32 + lane];
                acc.x += (v0.x + v1.x) + (v2.x + v3.x);
                acc.y += (v0.y + v1.y) + (v2.y + v3.y);
            }
            for (; j < e; j++) {
                int s0 = g_csr[j];
                float2 v0 = hs[(size_t)s0 * 32 + lane];
                acc.x += v0.x;
                acc.y += v0.y;
            }
            float d = g_dinv[node];
            acc.x *= d; acc.y *= d;
        }
        ((float2*)xs)[r * 33 + lane] = acc;
    }
    __syncthreads();

    int rg = t >> 4, cg = t & 15;
    for (int half = 0; half < 2; half++) {
        if (half) {
            __syncthreads();
            for (int i = t; i < 1024; i += 256) {
                int k = i >> 4, c4 = i & 15;
                ((float4*)ws)[i] = W24[(size_t)k * 32 + 16 + c4];
            }
            __syncthreads();
        }
        float a[4][4] = {};
#pragma unroll 8
        for (int k = 0; k < 64; k++) {
            float4 w = *(const float4*)&ws[k * 64 + cg * 4];
#pragma unroll
            for (int i = 0; i < 4; i++) {
                float xv = xs[(4 * rg + i) * 66 + k];
                a[i][0] += xv * w.x; a[i][1] += xv * w.y;
                a[i][2] += xv * w.z; a[i][3] += xv * w.w;
            }
        }
        float4 bb = __ldg((const float4*)&b2[half * 64 + cg * 4]);
#pragma unroll
        for (int i = 0; i < 4; i++) {
            int gr = row0 + 4 * rg + i;
            if (gr < N) {
                *(float4*)&g_h2[(size_t)gr * 128 + half * 64 + cg * 4] =
                    make_float4(fmaxf(a[i][0] + bb.x, 0.f), fmaxf(a[i][1] + bb.y, 0.f),
                                fmaxf(a[i][2] + bb.z, 0.f), fmaxf(a[i][3] + bb.w, 0.f));
            }
        }
    }
}

// ---------------------------------------------------------------------------
__global__ void k_offsets(const void* batch, int N) {
    int i = blockIdx.x * blockDim.x + threadIdx.x;
    if (i >= N) return;
    int b = load_idx(batch, i);
    int bp = (i == 0) ? -1 : load_idx(batch, i - 1);
    for (int g = bp + 1; g <= b; g++) g_off[g] = i;
    if (i == N - 1) {
        for (int g = b + 1; g <= NG; g++) g_off[g] = N;
    }
}

__global__ __launch_bounds__(1024) void k_pool(int N) {
    int g = blockIdx.x;
    int t = threadIdx.x;
    int c = t & 127;
    int grp = t >> 7;
    int s = g_off[g], e = g_off[g + 1];
    float sum = 0.f;
    for (int r = s + grp; r < e; r += 8) sum += g_h2[(size_t)r * 128 + c];
    __shared__ float sh[1024];
    sh[t] = sum;
    __syncthreads();
    if (grp == 0) {
        float tot = sh[c] + sh[c + 128] + sh[c + 256] + sh[c + 384] +
                    sh[c + 512] + sh[c + 640] + sh[c + 768] + sh[c + 896];
        g_pool[g * 128 + c] = tot / fmaxf((float)(e - s), 1.f);
    }
}

// ---------------------------------------------------------------------------
__global__ __launch_bounds__(512) void k_mlp(const float* __restrict__ M1, const float* __restrict__ c1,
                                             const float* __restrict__ M2, const float* __restrict__ c2,
                                             const float* __restrict__ M3, const float* __restrict__ c3,
                                             const float* __restrict__ M4, const float* __restrict__ c4,
                                             float* __restrict__ out) {
    __shared__ float sm[12288];
    float* A = sm;
    float* B = sm + 8192;
    int t = threadIdx.x;
    for (int i = t; i < 8192; i += 512) A[i] = g_pool[i];
    __syncthreads();

    int r = t >> 3;
    int c0 = (t & 7) * 8;

    {
        float acc[8] = {0, 0, 0, 0, 0, 0, 0, 0};
#pragma unroll 4
        for (int k = 0; k < 128; k++) {
            float a = A[r * 128 + k];
            float4 m0 = __ldg((const float4*)&M1[k * 64 + c0]);
            float4 m1 = __ldg((const float4*)&M1[k * 64 + c0 + 4]);
            acc[0] += a * m0.x; acc[1] += a * m0.y; acc[2] += a * m0.z; acc[3] += a * m0.w;
            acc[4] += a * m1.x; acc[5] += a * m1.y; acc[6] += a * m1.z; acc[7] += a * m1.w;
        }
#pragma unroll
        for (int j = 0; j < 8; j++) {
            float v = acc[j] + __ldg(&c1[c0 + j]);
            B[r * 64 + c0 + j] = (v > 0.f) ? v : 0.2f * v;
        }
    }
    __syncthreads();

    {
        float acc[8] = {0, 0, 0, 0, 0, 0, 0, 0};
#pragma unroll 4
        for (int k = 0; k < 64; k++) {
            float a = B[r * 64 + k];
            float4 m0 = __ldg((const float4*)&M2[k * 64 + c0]);
            float4 m1 = __ldg((const float4*)&M2[k * 64 + c0 + 4]);
            acc[0] += a * m0.x; acc[1] += a * m0.y; acc[2] += a * m0.z; acc[3] += a * m0.w;
            acc[4] += a * m1.x; acc[5] += a * m1.y; acc[6] += a * m1.z; acc[7] += a * m1.w;
        }
        __syncthreads();
#pragma unroll
        for (int j = 0; j < 8; j++) {
            float v = acc[j] + __ldg(&c2[c0 + j]);
            A[r * 64 + c0 + j] = (v > 0.f) ? v : 0.1f * v;
        }
    }
    __syncthreads();

    {
        float acc[8] = {0, 0, 0, 0, 0, 0, 0, 0};
#pragma unroll 4
        for (int k = 0; k < 64; k++) {
            float a = A[r * 64 + k];
            float4 m0 = __ldg((const float4*)&M3[k * 64 + c0]);
            float4 m1 = __ldg((const float4*)&M3[k * 64 + c0 + 4]);
            acc[0] += a * m0.x; acc[1] += a * m0.y; acc[2] += a * m0.z; acc[3] += a * m0.w;
            acc[4] += a * m1.x; acc[5] += a * m1.y; acc[6] += a * m1.z; acc[7] += a * m1.w;
        }
        __syncthreads();
#pragma unroll
        for (int j = 0; j < 8; j++) {
            float v = acc[j] + __ldg(&c3[c0 + j]);
            B[r * 64 + c0 + j] = (v > 0.f) ? v : 0.1f * v;
        }
    }
    __syncthreads();

    if (t < 64) {
        float s = 0.f;
#pragma unroll 4
        for (int k = 0; k < 64; k++) s += B[t * 64 + k] * __ldg(&M4[k]);
        s += __ldg(&c4[0]);
        out[t] = fmaxf(s, 0.f);
    }
}

// ---------------------------------------------------------------------------
extern "C" void kernel_launch(void* const* d_in, const int* in_sizes, int n_in,
                              void* d_out, int out_size) {
    const float* x  = (const float*)d_in[0];
    const void*  ei = d_in[1];
    const void*  bt = d_in[2];
    const float* W1 = (const float*)d_in[3];
    const float* b1 = (const float*)d_in[4];
    const float* W2 = (const float*)d_in[5];
    const float* b2 = (const float*)d_in[6];
    const float* M1 = (const float*)d_in[7];
    const float* c1 = (const float*)d_in[8];
    const float* M2 = (const float*)d_in[9];
    const float* c2 = (const float*)d_in[10];
    const float* M3 = (const float*)d_in[11];
    const float* c3 = (const float*)d_in[12];
    const float* M4 = (const float*)d_in[13];
    const float* c4 = (const float*)d_in[14];
    float* out = (float*)d_out;

    int E = in_sizes[1] / 2;   // 800000
    int N = in_sizes[2];       // 50000
    int NB = (N + 255) / 256;  // 196

    k_detect<<<1, 32>>>((const int*)ei);
    k_zero_cnt<<<(N + 255) / 256, 256>>>(N);
    k_hist<<<(E + 255) / 256, 256>>>(ei, E);
    k_blocksum<<<NB, 256>>>(N);
    k_scanb<<<1, 256>>>(NB, E, N);
    k_apply<<<NB, 256>>>(N);
    k_fill<<<(E + 255) / 256, 256>>>(ei, E);
    k_offsets<<<(N + 255) / 256, 256>>>(bt, N);

    k_gemm1<<<(N + 31) / 32, 128>>>(x, W1, N);
    k_agg0<<<(N + 7) / 8, 256>>>(b1, N);
    k_fused2<<<(N + 63) / 64, 256>>>(W2, b2, N);

    k_pool<<<NG, 1024>>>(N);
    k_mlp<<<1, 512>>>(M1, c1, M2, c2, M3, c3, M4, c4, out);
}

// round 7
// speedup vs baseline: 1.5983x; 1.0036x over previous
#include <cuda_runtime.h>
#include <math.h>

// GCNNet: 2x GCNConv(+self loops, sym norm) -> mean pool -> 4-layer MLP
// N=50000 nodes, E=800000 edges, 64 graphs, fp32 throughout.
//
//  - A(XW) == (AX)W : aggregate both layers at 64 channels.
//  - CSR build: histogram + device-wide scan (scan folded into apply).
//  - gemm1 writes UNSCALED xW and runs on a second stream, overlapped with
//    the whole CSR build (dinv[src] applied inside the agg0 gather).
//  - Layer-1 epilogue fused into agg0; layer-2 agg fused with GEMM2.
//  - detect+zero merged; offsets merged into apply. 10 launches total.

#define MAXN 50000
#define MAXE 800000
#define NG 64
#define NB_MAX 256

__device__ int   g_is64;
__device__ float g_dinv[MAXN];
__device__ int   g_cnt[MAXN];
__device__ int   g_rowstart[MAXN + 1];
__device__ int   g_cursor[MAXN];
__device__ int   g_csr[MAXE];
__device__ int   g_bsum[NB_MAX];
__device__ float g_hsA[MAXN * 64];
__device__ float g_hsB[MAXN * 64];
__device__ float g_h2[(size_t)MAXN * 128];
__device__ int   g_off[NG + 1];
__device__ float g_pool[NG * 128];

__device__ __forceinline__ int load_idx(const void* p, long long i) {
    return g_is64 ? (int)((const long long*)p)[i] : ((const int*)p)[i];
}

// Side stream + events for overlapping gemm1 with the CSR build.
// Created once at program load (host objects; no device-memory allocation).
namespace {
struct Aux {
    cudaStream_t s;
    cudaEvent_t fork, join;
    Aux() {
        cudaStreamCreateWithFlags(&s, cudaStreamNonBlocking);
        cudaEventCreateWithFlags(&fork, cudaEventDisableTiming);
        cudaEventCreateWithFlags(&join, cudaEventDisableTiming);
    }
};
Aux g_aux;
}

// ---------------------------------------------------------------------------
// zero histogram + dtype detection (block 0, warp 0).
__global__ void k_init(const int* ei_as_i32, int N) {
    int i = blockIdx.x * 256 + threadIdx.x;
    if (i < N) g_cnt[i] = 0;
    if (blockIdx.x == 0 && threadIdx.x < 32) {
        unsigned m = __ballot_sync(0xffffffffu, ei_as_i32[2 * threadIdx.x + 1] != 0);
        if (threadIdx.x == 0) g_is64 = (m == 0u) ? 1 : 0;
    }
}

__global__ void k_hist(const void* ei, int E) {
    int e = blockIdx.x * blockDim.x + threadIdx.x;
    if (e >= E) return;
    int d = load_idx(ei, (long long)E + e);
    atomicAdd(&g_cnt[d], 1);
}

__global__ void k_blocksum(int N) {
    int i = blockIdx.x * 256 + threadIdx.x;
    int v = (i < N) ? g_cnt[i] : 0;
#pragma unroll
    for (int o = 16; o; o >>= 1) v += __shfl_down_sync(0xffffffffu, v, o);
    __shared__ int ws[8];
    if ((threadIdx.x & 31) == 0) ws[threadIdx.x >> 5] = v;
    __syncthreads();
    if (threadIdx.x == 0) {
        int s = 0;
#pragma unroll
        for (int j = 0; j < 8; j++) s += ws[j];
        g_bsum[blockIdx.x] = s;
    }
}

// apply: every block scans g_bsum in shared (redundant, trivial), then does
// the intra-block scan -> rowstart/cursor/dinv. Also computes graph offsets.
__global__ __launch_bounds__(256) void k_apply(const void* bt, int NB, int E, int N) {
    __shared__ int sb[256];
    __shared__ int wt[8];
    __shared__ int wo[8];
    int t = threadIdx.x;

    sb[t] = (t < NB) ? g_bsum[t] : 0;
    __syncthreads();
    for (int o = 1; o < 256; o <<= 1) {
        int val = sb[t];
        int add = (t >= o) ? sb[t - o] : 0;
        __syncthreads();
        sb[t] = val + add;
        __syncthreads();
    }
    int blockoff = (blockIdx.x == 0) ? 0 : sb[blockIdx.x - 1];

    int i = blockIdx.x * 256 + t;
    int c = (i < N) ? g_cnt[i] : 0;
    int lane = t & 31, w = t >> 5;
    int x = c;
#pragma unroll
    for (int o = 1; o < 32; o <<= 1) {
        int y = __shfl_up_sync(0xffffffffu, x, o);
        if (lane >= o) x += y;
    }
    if (lane == 31) wt[w] = x;
    __syncthreads();
    if (t < 8) {
        int s = 0;
        for (int j = 0; j < t; j++) s += wt[j];
        wo[t] = s;
    }
    __syncthreads();
    if (i < N) {
        int excl = x - c + wo[w] + blockoff;
        g_rowstart[i] = excl;
        g_cursor[i]   = excl;
        g_dinv[i]     = rsqrtf((float)(c + 1));  // +1 self loop

        // graph offsets from sorted batch
        int b  = load_idx(bt, i);
        int bp = (i == 0) ? -1 : load_idx(bt, i - 1);
        for (int g = bp + 1; g <= b; g++) g_off[g] = i;
        if (i == N - 1) {
            for (int g = b + 1; g <= NG; g++) g_off[g] = N;
        }
    }
    if (i == 0) g_rowstart[N] = E;
}

__global__ void k_fill(const void* ei, int E) {
    int e = blockIdx.x * blockDim.x + threadIdx.x;
    if (e >= E) return;
    int d = load_idx(ei, (long long)E + e);
    int s = load_idx(ei, e);
    int pos = atomicAdd(&g_cursor[d], 1);
    g_csr[pos] = s;
}

// ---------------------------------------------------------------------------
// GEMM1: hsA[r][c] = (x[r] @ W1)[c]   (UNSCALED; dinv applied in agg0)
// 128 threads, 32 rows x 64 cols per block, 4x4 per thread, W1 K-halved.
__global__ __launch_bounds__(128) void k_gemm1(const float* __restrict__ x,
                                               const float* __restrict__ W1, int N) {
    __shared__ float xs[32 * 130];
    __shared__ float ws[64 * 64];
    int t = threadIdx.x;
    int row0 = blockIdx.x * 32;

    const float2* x2 = (const float2*)x;
#pragma unroll
    for (int j = 0; j < 16; j++) {
        int idx = t + j * 128;
        int r = idx >> 6, kk = idx & 63;
        int gr = row0 + r;
        float2 v = (gr < N) ? x2[(size_t)gr * 64 + kk] : make_float2(0.f, 0.f);
        ((float2*)xs)[r * 65 + kk] = v;
    }

    int rg = t >> 4, cg = t & 15;
    float a[4][4] = {};
    const float4* W14 = (const float4*)W1;
    for (int kh = 0; kh < 2; kh++) {
        __syncthreads();
        for (int i = t; i < 1024; i += 128) {
            int kl = i >> 4, c4 = i & 15;
            ((float4*)ws)[i] = W14[(size_t)(kh * 64 + kl) * 16 + c4];
        }
        __syncthreads();
#pragma unroll 8
        for (int k = 0; k < 64; k++) {
            float4 w = *(const float4*)&ws[k * 64 + cg * 4];
#pragma unroll
            for (int i = 0; i < 4; i++) {
                float xv = xs[(4 * rg + i) * 130 + kh * 64 + k];
                a[i][0] += xv * w.x; a[i][1] += xv * w.y;
                a[i][2] += xv * w.z; a[i][3] += xv * w.w;
            }
        }
    }
#pragma unroll
    for (int i = 0; i < 4; i++) {
        int gr = row0 + 4 * rg + i;
        if (gr < N) {
            *(float4*)&g_hsA[(size_t)gr * 64 + cg * 4] =
                make_float4(a[i][0], a[i][1], a[i][2], a[i][3]);
        }
    }
}

// ---------------------------------------------------------------------------
// agg0: hsB = relu( (Σ hsA[src]*dinv[src] + hsA[i]*dinv[i]) * dinv[i] + b1 ) * dinv[i]
__global__ __launch_bounds__(256) void k_agg0(const float* __restrict__ b1, int N) {
    const float2* hs = (const float2*)g_hsA;
    int warp = (blockIdx.x * blockDim.x + threadIdx.x) >> 5;
    int lane = threadIdx.x & 31;
    if (warp >= N) return;

    int s = g_rowstart[warp];
    int e = g_rowstart[warp + 1];
    float d = g_dinv[warp];
    float2 acc = hs[(size_t)warp * 32 + lane];  // self loop
    acc.x *= d; acc.y *= d;
    int j = s;
    for (; j + 3 < e; j += 4) {
        int s0 = g_csr[j], s1 = g_csr[j + 1], s2 = g_csr[j + 2], s3 = g_csr[j + 3];
        float d0 = g_dinv[s0], d1 = g_dinv[s1], d2 = g_dinv[s2], d3 = g_dinv[s3];
        float2 v0 = hs[(size_t)s0 * 32 + lane];
        float2 v1 = hs[(size_t)s1 * 32 + lane];
        float2 v2 = hs[(size_t)s2 * 32 + lane];
        float2 v3 = hs[(size_t)s3 * 32 + lane];
        acc.x += v0.x * d0 + v1.x * d1 + v2.x * d2 + v3.x * d3;
        acc.y += v0.y * d0 + v1.y * d1 + v2.y * d2 + v3.y * d3;
    }
    for (; j < e; j++) {
        int s0 = g_csr[j];
        float d0 = g_dinv[s0];
        float2 v0 = hs[(size_t)s0 * 32 + lane];
        acc.x += v0.x * d0;
        acc.y += v0.y * d0;
    }
    float2 bb = __ldg(&((const float2*)b1)[lane]);
    float2 o;
    o.x = fmaxf(acc.x * d + bb.x, 0.f) * d;
    o.y = fmaxf(acc.y * d + bb.y, 0.f) * d;
    ((float2*)g_hsB)[(size_t)warp * 32 + lane] = o;
}

// ---------------------------------------------------------------------------
// Fused layer-2: agg over hsB -> shared -> GEMM vs W2[64,128] (+b2, relu) -> h2
__global__ __launch_bounds__(256) void k_fused2(const float* __restrict__ W2,
                                                const float* __restrict__ b2, int N) {
    __shared__ float xs[64 * 66];
    __shared__ float ws[64 * 64];
    int t = threadIdx.x;
    int warp = t >> 5, lane = t & 31;
    int row0 = blockIdx.x * 64;
    const float4* W24 = (const float4*)W2;

    for (int i = t; i < 1024; i += 256) {
        int k = i >> 4, c4 = i & 15;
        ((float4*)ws)[i] = W24[(size_t)k * 32 + c4];
    }

    const float2* hs = (const float2*)g_hsB;
    for (int p = 0; p < 8; p++) {
        int r = p * 8 + warp;
        int node = row0 + r;
        float2 acc = make_float2(0.f, 0.f);
        if (node < N) {
            int s = g_rowstart[node], e = g_rowstart[node + 1];
            acc = hs[(size_t)node * 32 + lane];
            int j = s;
            for (; j + 3 < e; j += 4) {
                int s0 = g_csr[j], s1 = g_csr[j + 1], s2 = g_csr[j + 2], s3 = g_csr[j + 3];
                float2 v0 = hs[(size_t)s0 * 32 + lane];
                float2 v1 = hs[(size_t)s1 * 32 + lane];
                float2 v2 = hs[(size_t)s2 * 32 + lane];
                float2 v3 = hs[(size_t)s3 * 32 + lane];
                acc.x += (v0.x + v1.x) + (v2.x + v3.x);
                acc.y += (v0.y + v1.y) + (v2.y + v3.y);
            }
            for (; j < e; j++) {
                int s0 = g_csr[j];
                float2 v0 = hs[(size_t)s0 * 32 + lane];
                acc.x += v0.x;
                acc.y += v0.y;
            }
            float d = g_dinv[node];
            acc.x *= d; acc.y *= d;
        }
        ((float2*)xs)[r * 33 + lane] = acc;
    }
    __syncthreads();

    int rg = t >> 4, cg = t & 15;
    for (int half = 0; half < 2; half++) {
        if (half) {
            __syncthreads();
            for (int i = t; i < 1024; i += 256) {
                int k = i >> 4, c4 = i & 15;
                ((float4*)ws)[i] = W24[(size_t)k * 32 + 16 + c4];
            }
            __syncthreads();
        }
        float a[4][4] = {};
#pragma unroll 8
        for (int k = 0; k < 64; k++) {
            float4 w = *(const float4*)&ws[k * 64 + cg * 4];
#pragma unroll
            for (int i = 0; i < 4; i++) {
                float xv = xs[(4 * rg + i) * 66 + k];
                a[i][0] += xv * w.x; a[i][1] += xv * w.y;
                a[i][2] += xv * w.z; a[i][3] += xv * w.w;
            }
        }
        float4 bb = __ldg((const float4*)&b2[half * 64 + cg * 4]);
#pragma unroll
        for (int i = 0; i < 4; i++) {
            int gr = row0 + 4 * rg + i;
            if (gr < N) {
                *(float4*)&g_h2[(size_t)gr * 128 + half * 64 + cg * 4] =
                    make_float4(fmaxf(a[i][0] + bb.x, 0.f), fmaxf(a[i][1] + bb.y, 0.f),
                                fmaxf(a[i][2] + bb.z, 0.f), fmaxf(a[i][3] + bb.w, 0.f));
            }
        }
    }
}

// ---------------------------------------------------------------------------
__global__ __launch_bounds__(1024) void k_pool(int N) {
    int g = blockIdx.x;
    int t = threadIdx.x;
    int c = t & 127;
    int grp = t >> 7;
    int s = g_off[g], e = g_off[g + 1];
    float sum = 0.f;
    for (int r = s + grp; r < e; r += 8) sum += g_h2[(size_t)r * 128 + c];
    __shared__ float sh[1024];
    sh[t] = sum;
    __syncthreads();
    if (grp == 0) {
        float tot = sh[c] + sh[c + 128] + sh[c + 256] + sh[c + 384] +
                    sh[c + 512] + sh[c + 640] + sh[c + 768] + sh[c + 896];
        g_pool[g * 128 + c] = tot / fmaxf((float)(e - s), 1.f);
    }
}

// ---------------------------------------------------------------------------
__global__ __launch_bounds__(512) void k_mlp(const float* __restrict__ M1, const float* __restrict__ c1,
                                             const float* __restrict__ M2, const float* __restrict__ c2,
                                             const float* __restrict__ M3, const float* __restrict__ c3,
                                             const float* __restrict__ M4, const float* __restrict__ c4,
                                             float* __restrict__ out) {
    __shared__ float sm[12288];
    float* A = sm;
    float* B = sm + 8192;
    int t = threadIdx.x;
    for (int i = t; i < 8192; i += 512) A[i] = g_pool[i];
    __syncthreads();

    int r = t >> 3;
    int c0 = (t & 7) * 8;

    {
        float acc[8] = {0, 0, 0, 0, 0, 0, 0, 0};
#pragma unroll 4
        for (int k = 0; k < 128; k++) {
            float a = A[r * 128 + k];
            float4 m0 = __ldg((const float4*)&M1[k * 64 + c0]);
            float4 m1 = __ldg((const float4*)&M1[k * 64 + c0 + 4]);
            acc[0] += a * m0.x; acc[1] += a * m0.y; acc[2] += a * m0.z; acc[3] += a * m0.w;
            acc[4] += a * m1.x; acc[5] += a * m1.y; acc[6] += a * m1.z; acc[7] += a * m1.w;
        }
#pragma unroll
        for (int j = 0; j < 8; j++) {
            float v = acc[j] + __ldg(&c1[c0 + j]);
            B[r * 64 + c0 + j] = (v > 0.f) ? v : 0.2f * v;
        }
    }
    __syncthreads();

    {
        float acc[8] = {0, 0, 0, 0, 0, 0, 0, 0};
#pragma unroll 4
        for (int k = 0; k < 64; k++) {
            float a = B[r * 64 + k];
            float4 m0 = __ldg((const float4*)&M2[k * 64 + c0]);
            float4 m1 = __ldg((const float4*)&M2[k * 64 + c0 + 4]);
            acc[0] += a * m0.x; acc[1] += a * m0.y; acc[2] += a * m0.z; acc[3] += a * m0.w;
            acc[4] += a * m1.x; acc[5] += a * m1.y; acc[6] += a * m1.z; acc[7] += a * m1.w;
        }
        __syncthreads();
#pragma unroll
        for (int j = 0; j < 8; j++) {
            float v = acc[j] + __ldg(&c2[c0 + j]);
            A[r * 64 + c0 + j] = (v > 0.f) ? v : 0.1f * v;
        }
    }
    __syncthreads();

    {
        float acc[8] = {0, 0, 0, 0, 0, 0, 0, 0};
#pragma unroll 4
        for (int k = 0; k < 64; k++) {
            float a = A[r * 64 + k];
            float4 m0 = __ldg((const float4*)&M3[k * 64 + c0]);
            float4 m1 = __ldg((const float4*)&M3[k * 64 + c0 + 4]);
            acc[0] += a * m0.x; acc[1] += a * m0.y; acc[2] += a * m0.z; acc[3] += a * m0.w;
            acc[4] += a * m1.x; acc[5] += a * m1.y; acc[6] += a * m1.z; acc[7] += a * m1.w;
        }
        __syncthreads();
#pragma unroll
        for (int j = 0; j < 8; j++) {
            float v = acc[j] + __ldg(&c3[c0 + j]);
            B[r * 64 + c0 + j] = (v > 0.f) ? v : 0.1f * v;
        }
    }
    __syncthreads();

    if (t < 64) {
        float s = 0.f;
#pragma unroll 4
        for (int k = 0; k < 64; k++) s += B[t * 64 + k] * __ldg(&M4[k]);
        s += __ldg(&c4[0]);
        out[t] = fmaxf(s, 0.f);
    }
}

// ---------------------------------------------------------------------------
extern "C" void kernel_launch(void* const* d_in, const int* in_sizes, int n_in,
                              void* d_out, int out_size) {
    const float* x  = (const float*)d_in[0];
    const void*  ei = d_in[1];
    const void*  bt = d_in[2];
    const float* W1 = (const float*)d_in[3];
    const float* b1 = (const float*)d_in[4];
    const float* W2 = (const float*)d_in[5];
    const float* b2 = (const float*)d_in[6];
    const float* M1 = (const float*)d_in[7];
    const float* c1 = (const float*)d_in[8];
    const float* M2 = (const float*)d_in[9];
    const float* c2 = (const float*)d_in[10];
    const float* M3 = (const float*)d_in[11];
    const float* c3 = (const float*)d_in[12];
    const float* M4 = (const float*)d_in[13];
    const float* c4 = (const float*)d_in[14];
    float* out = (float*)d_out;

    int E = in_sizes[1] / 2;   // 800000
    int N = in_sizes[2];       // 50000
    int NB = (N + 255) / 256;  // 196

    // fork: gemm1 has no dependencies -> side stream, overlapped with CSR build
    cudaEventRecord(g_aux.fork, 0);
    cudaStreamWaitEvent(g_aux.s, g_aux.fork, 0);
    k_gemm1<<<(N + 31) / 32, 128, 0, g_aux.s>>>(x, W1, N);
    cudaEventRecord(g_aux.join, g_aux.s);

    // CSR build chain on the main stream
    k_init<<<NB, 256>>>((const int*)ei, N);
    k_hist<<<(E + 255) / 256, 256>>>(ei, E);
    k_blocksum<<<NB, 256>>>(N);
    k_apply<<<NB, 256>>>(bt, NB, E, N);
    k_fill<<<(E + 255) / 256, 256>>>(ei, E);

    // join: agg0 needs both gemm1 (hsA) and the CSR
    cudaStreamWaitEvent(0, g_aux.join, 0);
    k_agg0<<<(N + 7) / 8, 256>>>(b1, N);
    k_fused2<<<(N + 63) / 64, 256>>>(W2, b2, N);

    k_pool<<<NG, 1024>>>(N);
    k_mlp<<<1, 512>>>(M1, c1, M2, c2, M3, c3, M4, c4, out);
}

// round 8
// speedup vs baseline: 2.5380x; 1.5879x over previous
#include <cuda_runtime.h>
#include <math.h>

// GCNNet: 2x GCNConv(+self loops, sym norm) -> mean pool -> 4-layer MLP
// N=50000 nodes, E=800000 edges, 64 graphs, fp32 throughout.
//
//  - A(XW) == (AX)W : aggregate both layers at 64 channels.
//  - CSR build: histogram + device-wide scan (scan folded into apply).
//  - gemm1 writes UNSCALED xW (dinv[src] applied inside agg0 gather), so it
//    has no dependencies; placed 4th so ncu profiles it this round.
//  - Layer-1 epilogue fused into agg0; layer-2 agg fused with GEMM2.
//  - GEMM inner loops use float4 activation loads (fewer LDS issues).
//  - MLP: one block per graph (64 blocks) instead of one block total.

#define MAXN 50000
#define MAXE 800000
#define NG 64
#define NB_MAX 256

__device__ int   g_is64;
__device__ float g_dinv[MAXN];
__device__ int   g_cnt[MAXN];
__device__ int   g_rowstart[MAXN + 1];
__device__ int   g_cursor[MAXN];
__device__ int   g_csr[MAXE];
__device__ int   g_bsum[NB_MAX];
__device__ float g_hsA[MAXN * 64];
__device__ float g_hsB[MAXN * 64];
__device__ float g_h2[(size_t)MAXN * 128];
__device__ int   g_off[NG + 1];
__device__ float g_pool[NG * 128];

__device__ __forceinline__ int load_idx(const void* p, long long i) {
    return g_is64 ? (int)((const long long*)p)[i] : ((const int*)p)[i];
}

// ---------------------------------------------------------------------------
// zero histogram + dtype detection (block 0, warp 0).
__global__ void k_init(const int* ei_as_i32, int N) {
    int i = blockIdx.x * 256 + threadIdx.x;
    if (i < N) g_cnt[i] = 0;
    if (blockIdx.x == 0 && threadIdx.x < 32) {
        unsigned m = __ballot_sync(0xffffffffu, ei_as_i32[2 * threadIdx.x + 1] != 0);
        if (threadIdx.x == 0) g_is64 = (m == 0u) ? 1 : 0;
    }
}

__global__ void k_hist(const void* ei, int E) {
    int e = blockIdx.x * blockDim.x + threadIdx.x;
    if (e >= E) return;
    int d = load_idx(ei, (long long)E + e);
    atomicAdd(&g_cnt[d], 1);
}

__global__ void k_blocksum(int N) {
    int i = blockIdx.x * 256 + threadIdx.x;
    int v = (i < N) ? g_cnt[i] : 0;
#pragma unroll
    for (int o = 16; o; o >>= 1) v += __shfl_down_sync(0xffffffffu, v, o);
    __shared__ int ws[8];
    if ((threadIdx.x & 31) == 0) ws[threadIdx.x >> 5] = v;
    __syncthreads();
    if (threadIdx.x == 0) {
        int s = 0;
#pragma unroll
        for (int j = 0; j < 8; j++) s += ws[j];
        g_bsum[blockIdx.x] = s;
    }
}

// apply: every block scans g_bsum in shared (redundant, trivial), then the
// intra-block scan -> rowstart/cursor/dinv. Also computes graph offsets.
__global__ __launch_bounds__(256) void k_apply(const void* bt, int NB, int E, int N) {
    __shared__ int sb[256];
    __shared__ int wt[8];
    __shared__ int wo[8];
    int t = threadIdx.x;

    sb[t] = (t < NB) ? g_bsum[t] : 0;
    __syncthreads();
    for (int o = 1; o < 256; o <<= 1) {
        int val = sb[t];
        int add = (t >= o) ? sb[t - o] : 0;
        __syncthreads();
        sb[t] = val + add;
        __syncthreads();
    }
    int blockoff = (blockIdx.x == 0) ? 0 : sb[blockIdx.x - 1];

    int i = blockIdx.x * 256 + t;
    int c = (i < N) ? g_cnt[i] : 0;
    int lane = t & 31, w = t >> 5;
    int x = c;
#pragma unroll
    for (int o = 1; o < 32; o <<= 1) {
        int y = __shfl_up_sync(0xffffffffu, x, o);
        if (lane >= o) x += y;
    }
    if (lane == 31) wt[w] = x;
    __syncthreads();
    if (t < 8) {
        int s = 0;
        for (int j = 0; j < t; j++) s += wt[j];
        wo[t] = s;
    }
    __syncthreads();
    if (i < N) {
        int excl = x - c + wo[w] + blockoff;
        g_rowstart[i] = excl;
        g_cursor[i]   = excl;
        g_dinv[i]     = rsqrtf((float)(c + 1));  // +1 self loop

        int b  = load_idx(bt, i);
        int bp = (i == 0) ? -1 : load_idx(bt, i - 1);
        for (int g = bp + 1; g <= b; g++) g_off[g] = i;
        if (i == N - 1) {
            for (int g = b + 1; g <= NG; g++) g_off[g] = N;
        }
    }
    if (i == 0) g_rowstart[N] = E;
}

__global__ void k_fill(const void* ei, int E) {
    int e = blockIdx.x * blockDim.x + threadIdx.x;
    if (e >= E) return;
    int d = load_idx(ei, (long long)E + e);
    int s = load_idx(ei, e);
    int pos = atomicAdd(&g_cursor[d], 1);
    g_csr[pos] = s;
}

// ---------------------------------------------------------------------------
// GEMM1: hsA[r][c] = (x[r] @ W1)[c]   (UNSCALED; dinv applied in agg0)
// 128 threads, 32 rows x 64 cols per block, 4x4 per thread, W1 K-halved.
// xs stride 132 floats (16B-aligned rows, broadcast-friendly).
__global__ __launch_bounds__(128) void k_gemm1(const float* __restrict__ x,
                                               const float* __restrict__ W1, int N) {
    __shared__ float xs[32 * 132];
    __shared__ float ws[64 * 64];
    int t = threadIdx.x;
    int row0 = blockIdx.x * 32;

    const float2* x2 = (const float2*)x;
#pragma unroll
    for (int j = 0; j < 16; j++) {
        int idx = t + j * 128;
        int r = idx >> 6, kk = idx & 63;
        int gr = row0 + r;
        float2 v = (gr < N) ? x2[(size_t)gr * 64 + kk] : make_float2(0.f, 0.f);
        ((float2*)xs)[r * 66 + kk] = v;
    }

    int rg = t >> 4, cg = t & 15;
    float a[4][4] = {};
    const float4* W14 = (const float4*)W1;
    for (int kh = 0; kh < 2; kh++) {
        __syncthreads();
        for (int i = t; i < 1024; i += 128) {
            int kl = i >> 4, c4 = i & 15;
            ((float4*)ws)[i] = W14[(size_t)(kh * 64 + kl) * 16 + c4];
        }
        __syncthreads();
#pragma unroll
        for (int k = 0; k < 64; k += 4) {
            float4 xv[4];
#pragma unroll
            for (int i = 0; i < 4; i++)
                xv[i] = *(const float4*)&xs[(4 * rg + i) * 132 + kh * 64 + k];
#pragma unroll
            for (int kk = 0; kk < 4; kk++) {
                float4 w = *(const float4*)&ws[(k + kk) * 64 + cg * 4];
#pragma unroll
                for (int i = 0; i < 4; i++) {
                    float xvv = ((const float*)&xv[i])[kk];
                    a[i][0] += xvv * w.x; a[i][1] += xvv * w.y;
                    a[i][2] += xvv * w.z; a[i][3] += xvv * w.w;
                }
            }
        }
    }
#pragma unroll
    for (int i = 0; i < 4; i++) {
        int gr = row0 + 4 * rg + i;
        if (gr < N) {
            *(float4*)&g_hsA[(size_t)gr * 64 + cg * 4] =
                make_float4(a[i][0], a[i][1], a[i][2], a[i][3]);
        }
    }
}

// ---------------------------------------------------------------------------
// agg0: hsB = relu( (Σ hsA[src]*dinv[src] + hsA[i]*dinv[i]) * dinv[i] + b1 ) * dinv[i]
__global__ __launch_bounds__(256) void k_agg0(const float* __restrict__ b1, int N) {
    const float2* hs = (const float2*)g_hsA;
    int warp = (blockIdx.x * blockDim.x + threadIdx.x) >> 5;
    int lane = threadIdx.x & 31;
    if (warp >= N) return;

    int s = g_rowstart[warp];
    int e = g_rowstart[warp + 1];
    float d = g_dinv[warp];
    float2 acc = hs[(size_t)warp * 32 + lane];  // self loop
    acc.x *= d; acc.y *= d;
    int j = s;
    for (; j + 3 < e; j += 4) {
        int s0 = g_csr[j], s1 = g_csr[j + 1], s2 = g_csr[j + 2], s3 = g_csr[j + 3];
        float d0 = g_dinv[s0], d1 = g_dinv[s1], d2 = g_dinv[s2], d3 = g_dinv[s3];
        float2 v0 = hs[(size_t)s0 * 32 + lane];
        float2 v1 = hs[(size_t)s1 * 32 + lane];
        float2 v2 = hs[(size_t)s2 * 32 + lane];
        float2 v3 = hs[(size_t)s3 * 32 + lane];
        acc.x += v0.x * d0 + v1.x * d1 + v2.x * d2 + v3.x * d3;
        acc.y += v0.y * d0 + v1.y * d1 + v2.y * d2 + v3.y * d3;
    }
    for (; j < e; j++) {
        int s0 = g_csr[j];
        float d0 = g_dinv[s0];
        float2 v0 = hs[(size_t)s0 * 32 + lane];
        acc.x += v0.x * d0;
        acc.y += v0.y * d0;
    }
    float2 bb = __ldg(&((const float2*)b1)[lane]);
    float2 o;
    o.x = fmaxf(acc.x * d + bb.x, 0.f) * d;
    o.y = fmaxf(acc.y * d + bb.y, 0.f) * d;
    ((float2*)g_hsB)[(size_t)warp * 32 + lane] = o;
}

// ---------------------------------------------------------------------------
// Fused layer-2: agg over hsB -> shared -> GEMM vs W2[64,128] (+b2, relu) -> h2
// xs stride 68 floats (16B-aligned rows).
__global__ __launch_bounds__(256) void k_fused2(const float* __restrict__ W2,
                                                const float* __restrict__ b2, int N) {
    __shared__ float xs[64 * 68];
    __shared__ float ws[64 * 64];
    int t = threadIdx.x;
    int warp = t >> 5, lane = t & 31;
    int row0 = blockIdx.x * 64;
    const float4* W24 = (const float4*)W2;

    for (int i = t; i < 1024; i += 256) {
        int k = i >> 4, c4 = i & 15;
        ((float4*)ws)[i] = W24[(size_t)k * 32 + c4];
    }

    const float2* hs = (const float2*)g_hsB;
    for (int p = 0; p < 8; p++) {
        int r = p * 8 + warp;
        int node = row0 + r;
        float2 acc = make_float2(0.f, 0.f);
        if (node < N) {
            int s = g_rowstart[node], e = g_rowstart[node + 1];
            acc = hs[(size_t)node * 32 + lane];
            int j = s;
            for (; j + 3 < e; j += 4) {
                int s0 = g_csr[j], s1 = g_csr[j + 1], s2 = g_csr[j + 2], s3 = g_csr[j + 3];
                float2 v0 = hs[(size_t)s0 * 32 + lane];
                float2 v1 = hs[(size_t)s1 * 32 + lane];
                float2 v2 = hs[(size_t)s2 * 32 + lane];
                float2 v3 = hs[(size_t)s3 * 32 + lane];
                acc.x += (v0.x + v1.x) + (v2.x + v3.x);
                acc.y += (v0.y + v1.y) + (v2.y + v3.y);
            }
            for (; j < e; j++) {
                int s0 = g_csr[j];
                float2 v0 = hs[(size_t)s0 * 32 + lane];
                acc.x += v0.x;
                acc.y += v0.y;
            }
            float d = g_dinv[node];
            acc.x *= d; acc.y *= d;
        }
        ((float2*)xs)[r * 34 + lane] = acc;
    }
    __syncthreads();

    int rg = t >> 4, cg = t & 15;
    for (int half = 0; half < 2; half++) {
        if (half) {
            __syncthreads();
            for (int i = t; i < 1024; i += 256) {
                int k = i >> 4, c4 = i & 15;
                ((float4*)ws)[i] = W24[(size_t)k * 32 + 16 + c4];
            }
            __syncthreads();
        }
        float a[4][4] = {};
#pragma unroll
        for (int k = 0; k < 64; k += 4) {
            float4 xv[4];
#pragma unroll
            for (int i = 0; i < 4; i++)
                xv[i] = *(const float4*)&xs[(4 * rg + i) * 68 + k];
#pragma unroll
            for (int kk = 0; kk < 4; kk++) {
                float4 w = *(const float4*)&ws[(k + kk) * 64 + cg * 4];
#pragma unroll
                for (int i = 0; i < 4; i++) {
                    float xvv = ((const float*)&xv[i])[kk];
                    a[i][0] += xvv * w.x; a[i][1] += xvv * w.y;
                    a[i][2] += xvv * w.z; a[i][3] += xvv * w.w;
                }
            }
        }
        float4 bb = __ldg((const float4*)&b2[half * 64 + cg * 4]);
#pragma unroll
        for (int i = 0; i < 4; i++) {
            int gr = row0 + 4 * rg + i;
            if (gr < N) {
                *(float4*)&g_h2[(size_t)gr * 128 + half * 64 + cg * 4] =
                    make_float4(fmaxf(a[i][0] + bb.x, 0.f), fmaxf(a[i][1] + bb.y, 0.f),
                                fmaxf(a[i][2] + bb.z, 0.f), fmaxf(a[i][3] + bb.w, 0.f));
            }
        }
    }
}

// ---------------------------------------------------------------------------
__global__ __launch_bounds__(1024) void k_pool(int N) {
    int g = blockIdx.x;
    int t = threadIdx.x;
    int c = t & 127;
    int grp = t >> 7;
    int s = g_off[g], e = g_off[g + 1];
    float sum = 0.f;
    for (int r = s + grp; r < e; r += 8) sum += g_h2[(size_t)r * 128 + c];
    __shared__ float sh[1024];
    sh[t] = sum;
    __syncthreads();
    if (grp == 0) {
        float tot = sh[c] + sh[c + 128] + sh[c + 256] + sh[c + 384] +
                    sh[c + 512] + sh[c + 640] + sh[c + 768] + sh[c + 896];
        g_pool[g * 128 + c] = tot / fmaxf((float)(e - s), 1.f);
    }
}

// ---------------------------------------------------------------------------
// MLP: one block per graph, 64 threads. Layers: 128->64->64->64->1.
__global__ __launch_bounds__(64) void k_mlp(const float* __restrict__ M1, const float* __restrict__ c1,
                                            const float* __restrict__ M2, const float* __restrict__ c2,
                                            const float* __restrict__ M3, const float* __restrict__ c3,
                                            const float* __restrict__ M4, const float* __restrict__ c4,
                                            float* __restrict__ out) {
    int g = blockIdx.x;
    int t = threadIdx.x;
    __shared__ float A[128];
    __shared__ float B[64];
    __shared__ float C[64];
    __shared__ float red[64];

    A[t]      = g_pool[g * 128 + t];
    A[t + 64] = g_pool[g * 128 + 64 + t];
    __syncthreads();

    // L1: B = leaky0.2(A @ M1[128,64] + c1)
    {
        float acc = 0.f;
#pragma unroll 4
        for (int k = 0; k < 128; k++) acc += A[k] * __ldg(&M1[k * 64 + t]);
        float v = acc + __ldg(&c1[t]);
        B[t] = (v > 0.f) ? v : 0.2f * v;
    }
    __syncthreads();

    // L2: C = leaky0.1(B @ M2[64,64] + c2)
    {
        float acc = 0.f;
#pragma unroll 4
        for (int k = 0; k < 64; k++) acc += B[k] * __ldg(&M2[k * 64 + t]);
        float v = acc + __ldg(&c2[t]);
        C[t] = (v > 0.f) ? v : 0.1f * v;
    }
    __syncthreads();

    // L3: red = leaky0.1(C @ M3[64,64] + c3) (store into red buffer)
    {
        float acc = 0.f;
#pragma unroll 4
        for (int k = 0; k < 64; k++) acc += C[k] * __ldg(&M3[k * 64 + t]);
        float v = acc + __ldg(&c3[t]);
        red[t] = (v > 0.f) ? v : 0.1f * v;
    }
    __syncthreads();

    // L4: out[g] = relu(red @ M4[64,1] + c4)
    float p = red[t] * __ldg(&M4[t]);
    __syncthreads();
    red[t] = p;
    __syncthreads();
    if (t < 32) {
        float v = red[t] + red[t + 32];
#pragma unroll
        for (int o = 16; o; o >>= 1) v += __shfl_down_sync(0xffffffffu, v, o);
        if (t == 0) out[g] = fmaxf(v + __ldg(&c4[0]), 0.f);
    }
}

// ---------------------------------------------------------------------------
extern "C" void kernel_launch(void* const* d_in, const int* in_sizes, int n_in,
                              void* d_out, int out_size) {
    const float* x  = (const float*)d_in[0];
    const void*  ei = d_in[1];
    const void*  bt = d_in[2];
    const float* W1 = (const float*)d_in[3];
    const float* b1 = (const float*)d_in[4];
    const float* W2 = (const float*)d_in[5];
    const float* b2 = (const float*)d_in[6];
    const float* M1 = (const float*)d_in[7];
    const float* c1 = (const float*)d_in[8];
    const float* M2 = (const float*)d_in[9];
    const float* c2 = (const float*)d_in[10];
    const float* M3 = (const float*)d_in[11];
    const float* c3 = (const float*)d_in[12];
    const float* M4 = (const float*)d_in[13];
    const float* c4 = (const float*)d_in[14];
    float* out = (float*)d_out;

    int E = in_sizes[1] / 2;   // 800000
    int N = in_sizes[2];       // 50000
    int NB = (N + 255) / 256;  // 196

    k_init<<<NB, 256>>>((const int*)ei, N);
    k_hist<<<(E + 255) / 256, 256>>>(ei, E);
    k_blocksum<<<NB, 256>>>(N);
    k_gemm1<<<(N + 31) / 32, 128>>>(x, W1, N);   // 4th: gets profiled by ncu
    k_apply<<<NB, 256>>>(bt, NB, E, N);
    k_fill<<<(E + 255) / 256, 256>>>(ei, E);
    k_agg0<<<(N + 7) / 8, 256>>>(b1, N);
    k_fused2<<<(N + 63) / 64, 256>>>(W2, b2, N);
    k_pool<<<NG, 1024>>>(N);
    k_mlp<<<NG, 64>>>(M1, c1, M2, c2, M3, c3, M4, c4, out);
}